// round 11
// baseline (speedup 1.0000x reference)
#include <cuda_runtime.h>
#include <cuda_fp16.h>
#include <math.h>
#include <stdint.h>

// Problem constants
#define N1 400000
#define N2 400000
#define N3 800000
#define N4 1200000
#define U  128
#define NTHR 512     // 16 warps: 4 m-warps x 4 n-warps, warp tile 32x32
#define PW  68       // tile pitch in half2 words (64 data + 4 pad)
#define TILE_WORDS 8704   // 128 rows x 68 words

// ---------------------------------------------------------------------------
// Scratch buffers
// ---------------------------------------------------------------------------
__device__ uint32_t g_H2h[(size_t)N2 * 64];   // fp16 half2 rows
__device__ uint32_t g_H3h[(size_t)N3 * 64];
__device__ float    g_HD3[(size_t)N3 * U];
__device__ float    g_HD2[(size_t)N2 * U];
__device__ float    g_HD1[(size_t)N1 * U];
// 21 weight chunk images (n-major: word[n*68+k2] = half2(k=2k2, 2k2+1) at col n)
__device__ uint32_t g_WT[21 * TILE_WORDS];

// chunk indices into g_WT
#define CH_UP2 0
#define CH_UP3 3
#define CH_UP4 6
#define CH_DN3 9
#define CH_DN2 11
#define CH_DN1 13
#define CH_W2(i) (15 + (i))   // 0=up2 1=up3 2=up4 3=dn3 4=dn2 5=dn1

// ---------------------------------------------------------------------------
// helpers
// ---------------------------------------------------------------------------
__device__ __forceinline__ float fast_tanh(float x) {
    float e = __expf(2.0f * x);
    return 1.0f - __fdividef(2.0f, e + 1.0f);
}
__device__ __forceinline__ uint32_t h2bits(__half2 h) { return *(uint32_t*)&h; }
__device__ __forceinline__ uint32_t pack2(float x, float y) {
    return h2bits(__floats2half2_rn(x, y));
}
__device__ __forceinline__ void red_add_v2(float* p, float x, float y) {
    asm volatile("red.global.add.v2.f32 [%0], {%1,%2};"
                 :: "l"(p), "f"(x), "f"(y) : "memory");
}
__device__ __forceinline__ void mma_fp16(float c[4],
                                         uint32_t a0, uint32_t a1, uint32_t a2, uint32_t a3,
                                         uint32_t b0, uint32_t b1) {
    asm volatile(
        "mma.sync.aligned.m16n8k16.row.col.f32.f16.f16.f32 "
        "{%0,%1,%2,%3}, {%4,%5,%6,%7}, {%8,%9}, {%0,%1,%2,%3};"
        : "+f"(c[0]), "+f"(c[1]), "+f"(c[2]), "+f"(c[3])
        : "r"(a0), "r"(a1), "r"(a2), "r"(a3), "r"(b0), "r"(b1));
}

// ---------------------------------------------------------------------------
// Weight prep (ONE launch): all 21 chunks -> n-major fp16 tile images.
// ---------------------------------------------------------------------------
struct PrepPtrs { const float* p[21]; };

__global__ void prep_all(PrepPtrs pp, uint32_t* __restrict__ dst)
{
    int e = blockIdx.x * 256 + threadIdx.x;
    if (e >= 21 * TILE_WORDS) return;
    int chunk = e / TILE_WORDS, w = e - chunk * TILE_WORDS;
    int n = w / PW, k2 = w - n * PW;
    uint32_t v = 0;
    if (k2 < 64) {
        const float* W = pp.p[chunk];
        v = pack2(W[(size_t)(2 * k2) * 128 + n], W[(size_t)(2 * k2 + 1) * 128 + n]);
    }
    dst[e] = v;
}

// single zero kernel for all three scatter targets
__global__ void zero_all(float4* __restrict__ hd3, float4* __restrict__ hd2,
                         float4* __restrict__ hd1)
{
    const long Z3 = (long)N3 * 32, Z2 = (long)N2 * 32, Z1 = (long)N1 * 32;
    long i = (long)blockIdx.x * 256 + threadIdx.x;
    if (i >= Z3 + Z2 + Z1) return;
    float4 z = make_float4(0.f, 0.f, 0.f, 0.f);
    if (i < Z3)           hd3[i] = z;
    else if (i < Z3 + Z2) hd2[i - Z3] = z;
    else                  hd1[i - Z3 - Z2] = z;
}

// ---------------------------------------------------------------------------
// fp16 fused gather + MLP (+ fused scatter), mma m16n8k16.
// All tile loads are LDG.128 held-in-regs -> STS.128 (no cp.async: its 8cyc
// per-16B issue cost was the pipeline bottleneck). One __syncthreads/segment.
// CTA tile 128x128, 512 threads, 16 warps (4m x 4n), warp tile 32x32.
// ---------------------------------------------------------------------------
template <int NSEG, bool SCATTER, bool SELF16, bool GAT16, bool OUT16>
__global__ __launch_bounds__(NTHR, 1)
void mlp_fp16(const void* __restrict__ selfp,
              const void* __restrict__ gatp,
              const int*  __restrict__ idxg,
              const uint32_t* __restrict__ WB1,   // NSEG chunk images
              const float* __restrict__ b1,
              const uint32_t* __restrict__ WB2,   // 1 chunk image
              const float* __restrict__ b2,
              void* __restrict__ outp,
              const int* __restrict__ idxs)
{
    extern __shared__ uint32_t smu[];
    uint32_t* Ab[2] = { smu,                smu + TILE_WORDS };
    uint32_t* Bb[2] = { smu + 2*TILE_WORDS, smu + 3*TILE_WORDS };

    const int t    = threadIdx.x;
    const int lane = t & 31;
    const int wid  = t >> 5;
    const int g    = lane >> 2;
    const int tg   = lane & 3;
    const int wm   = (wid & 3) * 32;    // 4 m-warps
    const int wn   = (wid >> 2) * 32;   // 4 n-warps
    const long r0  = (long)blockIdx.x * 128;
    const int arow = t >> 2;            // A-fill: 4 threads per row
    const int aq   = t & 3;             // quarter of the row

    const uint32_t smemU = (uint32_t)__cvta_generic_to_shared(smu);
    const uint32_t Aaddr[2] = { smemU,                  smemU + TILE_WORDS*4 };
    const uint32_t Baddr[2] = { smemU + 2*TILE_WORDS*4, smemU + 3*TILE_WORDS*4 };

    // ldmatrix lane offsets (bytes) — identical to round 10 (verified)
    const uint32_t aLane = ((wm + (lane & 15)) * PW + (lane >> 4) * 4) * 4;
    const uint32_t bLane = ((wn + (lane & 7) + ((lane >> 4) << 3)) * PW
                            + ((lane >> 3) & 1) * 4) * 4;

    // gather row indices
    long rows[3];
    rows[0] = r0 + arow;
    if (NSEG == 3) {
        int2 gi = __ldg((const int2*)idxg + (r0 + arow));
        rows[1] = gi.x; rows[2] = gi.y;
    } else {
        rows[1] = r0 + arow;
    }

    float accf[2][4][4];
#pragma unroll
    for (int mt = 0; mt < 2; mt++)
#pragma unroll
        for (int nt = 0; nt < 4; nt++)
#pragma unroll
            for (int c = 0; c < 4; c++) accf[mt][nt][c] = 0.f;

    // ---- load/store helpers (held-in-register pipeline) ----
    auto ldA16 = [&](int seg, uint4 h[4]) {
        const uint4* src = (const uint4*)(seg == 0 ? selfp : gatp)
                           + rows[seg] * 16 + aq * 4;
#pragma unroll
        for (int i = 0; i < 4; i++) h[i] = __ldg(src + i);
    };
    auto stA16 = [&](const uint4 h[4], uint32_t* dstA) {
        uint4* d = (uint4*)(dstA + arow * PW + aq * 16);
#pragma unroll
        for (int i = 0; i < 4; i++) d[i] = h[i];
    };
    auto ldA32 = [&](int seg, float4 h[8]) {
        const float4* src = (const float4*)(seg == 0 ? selfp : gatp)
                            + rows[seg] * 32 + aq * 8;
#pragma unroll
        for (int i = 0; i < 8; i++) h[i] = __ldg(src + i);
    };
    auto stA32 = [&](const float4 h[8], uint32_t* dstA) {
        uint4* d = (uint4*)(dstA + arow * PW + aq * 16);
#pragma unroll
        for (int i = 0; i < 4; i++) {
            uint4 w;
            w.x = pack2(h[2*i].x,   h[2*i].y);
            w.y = pack2(h[2*i].z,   h[2*i].w);
            w.z = pack2(h[2*i+1].x, h[2*i+1].y);
            w.w = pack2(h[2*i+1].z, h[2*i+1].w);
            d[i] = w;
        }
    };
    auto ldB = [&](const uint32_t* src, uint4 h[5]) {
        const uint4* s = (const uint4*)src;
#pragma unroll
        for (int i = 0; i < 4; i++) h[i] = __ldg(s + t + i * NTHR);
        if (t < 128) h[4] = __ldg(s + 2048 + t);
    };
    auto stB = [&](const uint4 h[5], uint32_t* dstB) {
        uint4* d = (uint4*)dstB;
#pragma unroll
        for (int i = 0; i < 4; i++) d[t + i * NTHR] = h[i];
        if (t < 128) d[2048 + t] = h[4];
    };

    auto gemm = [&](uint32_t Aa, uint32_t Ba) {
#pragma unroll
        for (int k = 0; k < 8; k++) {
            uint32_t a[2][4], b[4][2];
#pragma unroll
            for (int mt = 0; mt < 2; mt++)
                asm volatile(
                    "ldmatrix.sync.aligned.m8n8.x4.shared.b16 {%0,%1,%2,%3}, [%4];"
                    : "=r"(a[mt][0]), "=r"(a[mt][1]), "=r"(a[mt][2]), "=r"(a[mt][3])
                    : "r"(Aa + aLane + mt * 4352 + k * 32));
#pragma unroll
            for (int nh = 0; nh < 2; nh++)
                asm volatile(
                    "ldmatrix.sync.aligned.m8n8.x4.shared.b16 {%0,%1,%2,%3}, [%4];"
                    : "=r"(b[2*nh][0]), "=r"(b[2*nh][1]),
                      "=r"(b[2*nh+1][0]), "=r"(b[2*nh+1][1])
                    : "r"(Ba + bLane + nh * 4352 + k * 32));
#pragma unroll
            for (int mt = 0; mt < 2; mt++)
#pragma unroll
                for (int nt = 0; nt < 4; nt++)
                    mma_fp16(accf[mt][nt], a[mt][0], a[mt][1], a[mt][2], a[mt][3],
                             b[nt][0], b[nt][1]);
        }
    };

    // ---- prologue: segment 0 tiles (direct ld+st) ----
    if (SELF16) {
        uint4 h[4]; ldA16(0, h); stA16(h, Ab[0]);
    } else {
        float4 h[8]; ldA32(0, h); stA32(h, Ab[0]);
    }
    { uint4 hb[5]; ldB(WB1, hb); stB(hb, Bb[0]); }

    // ---- Phase 1: D = X @ W1 over NSEG K-segments of 128 ----
#pragma unroll
    for (int seg = 0; seg < NSEG; seg++) {
        __syncthreads();            // tiles[seg] visible; free buffer safe
        uint4  ha16[4];
        float4 ha32[8];
        uint4  hb[5];
        const bool haveA = (seg + 1 < NSEG);
        if (haveA) {
            if (GAT16) ldA16(seg + 1, ha16);
            else       ldA32(seg + 1, ha32);
            ldB(WB1 + (size_t)(seg + 1) * TILE_WORDS, hb);
        } else {
            ldB(WB2, hb);           // W2 prefetch for phase 2
        }
        gemm(Aaddr[seg & 1], Baddr[seg & 1]);
        if (haveA) {
            if (GAT16) stA16(ha16, Ab[(seg + 1) & 1]);
            else       stA32(ha32, Ab[(seg + 1) & 1]);
        }
        stB(hb, Bb[(seg + 1) & 1]);
    }

    // ---- H = fp16(tanh(acc + b1)) -> A[NSEG&1] (free buffer) ----
    {
        uint32_t* Ah = Ab[NSEG & 1];
#pragma unroll
        for (int nt = 0; nt < 4; nt++) {
            int col = wn + nt * 8 + 2 * tg;
            float bx = __ldg(&b1[col]), by = __ldg(&b1[col + 1]);
            int wc = col >> 1;
#pragma unroll
            for (int mt = 0; mt < 2; mt++) {
                int row = wm + mt * 16 + g;
                Ah[row * PW + wc] =
                    pack2(fast_tanh(accf[mt][nt][0] + bx),
                          fast_tanh(accf[mt][nt][1] + by));
                Ah[(row + 8) * PW + wc] =
                    pack2(fast_tanh(accf[mt][nt][2] + bx),
                          fast_tanh(accf[mt][nt][3] + by));
                accf[mt][nt][0] = 0.f; accf[mt][nt][1] = 0.f;
                accf[mt][nt][2] = 0.f; accf[mt][nt][3] = 0.f;
            }
        }
    }
    __syncthreads();

    // ---- Phase 2: Y = H @ W2 ----
    gemm(Aaddr[NSEG & 1], Baddr[NSEG & 1]);

    // ---- epilogue: bias2 + (scatter | fp16 store | f32 store) ----
    float bx[4], by[4];
#pragma unroll
    for (int nt = 0; nt < 4; nt++) {
        int col = wn + nt * 8 + 2 * tg;
        bx[nt] = __ldg(&b2[col]);
        by[nt] = __ldg(&b2[col + 1]);
    }
#pragma unroll
    for (int mt = 0; mt < 2; mt++) {
        long ga = r0 + wm + mt * 16 + g;    // rows ga, ga+8
        if (SCATTER) {
            float* dst = (float*)outp;
            int2 pa = __ldg((const int2*)idxs + ga);
            int2 pb = __ldg((const int2*)idxs + ga + 8);
#pragma unroll
            for (int nt = 0; nt < 4; nt++) {
                int col = wn + nt * 8 + 2 * tg;
                float x0 = accf[mt][nt][0] + bx[nt], y0 = accf[mt][nt][1] + by[nt];
                float x1 = accf[mt][nt][2] + bx[nt], y1 = accf[mt][nt][3] + by[nt];
                red_add_v2(dst + (long)pa.x * U + col, x0, y0);
                red_add_v2(dst + (long)pa.y * U + col, x0, y0);
                red_add_v2(dst + (long)pb.x * U + col, x1, y1);
                red_add_v2(dst + (long)pb.y * U + col, x1, y1);
            }
        } else if (OUT16) {
            uint32_t* dst = (uint32_t*)outp;
#pragma unroll
            for (int nt = 0; nt < 4; nt++) {
                int col = wn + nt * 8 + 2 * tg;
                dst[ga * 64 + (col >> 1)] =
                    pack2(accf[mt][nt][0] + bx[nt], accf[mt][nt][1] + by[nt]);
                dst[(ga + 8) * 64 + (col >> 1)] =
                    pack2(accf[mt][nt][2] + bx[nt], accf[mt][nt][3] + by[nt]);
            }
        } else {
            float* dst = (float*)outp;
#pragma unroll
            for (int nt = 0; nt < 4; nt++) {
                int col = wn + nt * 8 + 2 * tg;
                *(float2*)&dst[ga * U + col] =
                    make_float2(accf[mt][nt][0] + bx[nt], accf[mt][nt][1] + by[nt]);
                *(float2*)&dst[(ga + 8) * U + col] =
                    make_float2(accf[mt][nt][2] + bx[nt], accf[mt][nt][3] + by[nt]);
            }
        }
    }
}

// ---------------------------------------------------------------------------
// Launch sequence: prep(1), zero_all(2), then 6 MLPs — ncu window lands on MLP
// ---------------------------------------------------------------------------
extern "C" void kernel_launch(void* const* d_in, const int* in_sizes, int n_in,
                              void* d_out, int out_size)
{
    const float* h1 = (const float*)d_in[0];
    const float* h2 = (const float*)d_in[1];
    const float* h3 = (const float*)d_in[2];
    const float* h4 = (const float*)d_in[3];
    const int* idx2 = (const int*)d_in[4];
    const int* idx3 = (const int*)d_in[5];
    const int* idx4 = (const int*)d_in[6];

    const float* up2W1 = (const float*)d_in[7],  *up2b1 = (const float*)d_in[8],
               * up2W2 = (const float*)d_in[9],  *up2b2 = (const float*)d_in[10];
    const float* up3W1 = (const float*)d_in[11], *up3b1 = (const float*)d_in[12],
               * up3W2 = (const float*)d_in[13], *up3b2 = (const float*)d_in[14];
    const float* up4W1 = (const float*)d_in[15], *up4b1 = (const float*)d_in[16],
               * up4W2 = (const float*)d_in[17], *up4b2 = (const float*)d_in[18];
    const float* dn1W1 = (const float*)d_in[19], *dn1b1 = (const float*)d_in[20],
               * dn1W2 = (const float*)d_in[21], *dn1b2 = (const float*)d_in[22];
    const float* dn2W1 = (const float*)d_in[23], *dn2b1 = (const float*)d_in[24],
               * dn2W2 = (const float*)d_in[25], *dn2b2 = (const float*)d_in[26];
    const float* dn3W1 = (const float*)d_in[27], *dn3b1 = (const float*)d_in[28],
               * dn3W2 = (const float*)d_in[29], *dn3b2 = (const float*)d_in[30];

    float* out = (float*)d_out;

    uint32_t *H2h, *H3h, *WT;
    float *HD3, *HD2, *HD1;
    cudaGetSymbolAddress((void**)&H2h, g_H2h);
    cudaGetSymbolAddress((void**)&H3h, g_H3h);
    cudaGetSymbolAddress((void**)&HD3, g_HD3);
    cudaGetSymbolAddress((void**)&HD2, g_HD2);
    cudaGetSymbolAddress((void**)&HD1, g_HD1);
    cudaGetSymbolAddress((void**)&WT,  g_WT);

    const size_t SMEM = (size_t)4 * TILE_WORDS * 4;   // 139264 B
    cudaFuncSetAttribute((const void*)mlp_fp16<3,false,false,false,true >, cudaFuncAttributeMaxDynamicSharedMemorySize, (int)SMEM);
    cudaFuncSetAttribute((const void*)mlp_fp16<3,false,false,true, true >, cudaFuncAttributeMaxDynamicSharedMemorySize, (int)SMEM);
    cudaFuncSetAttribute((const void*)mlp_fp16<3,true, false,true, false>, cudaFuncAttributeMaxDynamicSharedMemorySize, (int)SMEM);
    cudaFuncSetAttribute((const void*)mlp_fp16<2,true, true, false,false>, cudaFuncAttributeMaxDynamicSharedMemorySize, (int)SMEM);
    cudaFuncSetAttribute((const void*)mlp_fp16<2,false,false,false,false>, cudaFuncAttributeMaxDynamicSharedMemorySize, (int)SMEM);

    // ---- single weight-prep launch ----
    {
        PrepPtrs pp;
        const float* w1s[6] = {up2W1, up3W1, up4W1, dn3W1, dn2W1, dn1W1};
        const int   nch[6]  = {3, 3, 3, 2, 2, 2};
        int c = 0;
        for (int s = 0; s < 6; s++)
            for (int j = 0; j < nch[s]; j++) pp.p[c++] = w1s[s] + (size_t)j * 16384;
        const float* w2s[6] = {up2W2, up3W2, up4W2, dn3W2, dn2W2, dn1W2};
        for (int s = 0; s < 6; s++) pp.p[c++] = w2s[s];
        prep_all<<<(21 * TILE_WORDS + 255) / 256, 256>>>(pp, WT);
    }

    // ---- single zero launch (scatter targets) ----
    {
        long tot = (long)(N3 + N2 + N1) * 32;
        zero_all<<<(int)((tot + 255) / 256), 256>>>((float4*)HD3, (float4*)HD2,
                                                    (float4*)HD1);
    }

    const int g1 = N1 / 128, g2 = N2 / 128, g3 = N3 / 128, g4 = N4 / 128;

    // ---- upward pass ----
    mlp_fp16<3,false,false,false,true ><<<g2, NTHR, SMEM>>>(
        h2, h1, idx2, WT + (size_t)CH_UP2 * TILE_WORDS, up2b1,
        WT + (size_t)CH_W2(0) * TILE_WORDS, up2b2, H2h, nullptr);
    mlp_fp16<3,false,false,true ,true ><<<g3, NTHR, SMEM>>>(
        h3, H2h, idx3, WT + (size_t)CH_UP3 * TILE_WORDS, up3b1,
        WT + (size_t)CH_W2(1) * TILE_WORDS, up3b2, H3h, nullptr);
    mlp_fp16<3,true ,false,true ,false><<<g4, NTHR, SMEM>>>(
        h4, H3h, idx4, WT + (size_t)CH_UP4 * TILE_WORDS, up4b1,
        WT + (size_t)CH_W2(2) * TILE_WORDS, up4b2, HD3, idx4);

    // ---- downward pass ----
    mlp_fp16<2,true ,true ,false,false><<<g3, NTHR, SMEM>>>(
        H3h, HD3, nullptr, WT + (size_t)CH_DN3 * TILE_WORDS, dn3b1,
        WT + (size_t)CH_W2(3) * TILE_WORDS, dn3b2, HD2, idx3);
    mlp_fp16<2,true ,true ,false,false><<<g2, NTHR, SMEM>>>(
        H2h, HD2, nullptr, WT + (size_t)CH_DN2 * TILE_WORDS, dn2b1,
        WT + (size_t)CH_W2(4) * TILE_WORDS, dn2b2, HD1, idx2);
    mlp_fp16<2,false,false,false,false><<<g1, NTHR, SMEM>>>(
        h1, HD1, nullptr, WT + (size_t)CH_DN1 * TILE_WORDS, dn1b1,
        WT + (size_t)CH_W2(5) * TILE_WORDS, dn1b2, out, nullptr);
}